// round 2
// baseline (speedup 1.0000x reference)
#include <cuda_runtime.h>

#define NMAX    50048
#define EMAX    800000
#define ETOTMAX (NMAX + EMAX)

// ------------------------- scratch (device globals) -------------------------
__device__ __align__(16) float    g_xl1[NMAX * 128];
__device__ __align__(16) float    g_xr1[NMAX * 128];
__device__ __align__(16) float    g_agg1[NMAX * 128];
__device__ __align__(16) float    g_h1[NMAX * 128];
__device__ __align__(16) float    g_xl2[NMAX * 64];
__device__ __align__(16) float    g_xr2[NMAX * 64];
__device__ __align__(16) float    g_agg2[NMAX * 64];
__device__ __align__(16) float    g_h2[NMAX * 64];
__device__ __align__(16) float    g_ex[(size_t)ETOTMAX * 8];  // per-edge logits -> exp
__device__ __align__(16) unsigned g_mu[NMAX * 8];             // segment max (ordered uint)
__device__ __align__(16) float    g_den[NMAX * 8];            // softmax denominator
__device__ __align__(16) int      g_src[ETOTMAX];
__device__ __align__(16) int      g_dst[ETOTMAX];

// ------------------------- helpers -------------------------
__device__ __forceinline__ unsigned ford(float f) {
    unsigned u = __float_as_uint(f);
    return (u & 0x80000000u) ? ~u : (u | 0x80000000u);
}
__device__ __forceinline__ float funord(unsigned u) {
    return (u & 0x80000000u) ? __uint_as_float(u ^ 0x80000000u) : __uint_as_float(~u);
}
__device__ __forceinline__ float elu1(float v) { return v > 0.f ? v : expm1f(v); }

// ------------------------- edge index copy (+ self loops) -------------------------
// edge_index is int32 on device (JAX x64 disabled downcasts int64 -> int32)
__global__ void k_edges(const int* __restrict__ ei, int E, int N) {
    int i = blockIdx.x * blockDim.x + threadIdx.x;
    int tot = E + N;
    if (i < tot) {
        if (i < E) {
            g_src[i] = ei[i];
            g_dst[i] = ei[E + i];
        } else {
            g_src[i] = i - E;
            g_dst[i] = i - E;
        }
    }
}

// ------------------------- zero init per layer -------------------------
template <int LAYER>
__global__ void k_zero(int N) {
    const int HC = (LAYER == 1) ? 128 : 64;
    const int H  = (LAYER == 1) ? 8 : 1;
    float* agg = (LAYER == 1) ? g_agg1 : g_agg2;
    int i = blockIdx.x * blockDim.x + threadIdx.x;
    if (i < N * HC) agg[i] = 0.f;
    if (i < N * H) { g_mu[i] = 0u; g_den[i] = 0.f; }
}

// ------------------------- tiled SGEMM: C = A[M,K] @ W[K,Nout] + bias (+opt ELU) ---------
// BM=BN=64, BK=16, 256 threads, 4x4 microtile.
// SRC selects A: 0=arg, 1=g_h1, 2=g_h2.  DST selects C: 0=arg, 1..4 = xl1,xr1,xl2,xr2.
template <int K, int ACT, int SRC, int DST>
__global__ __launch_bounds__(256) void k_gemm(const float* __restrict__ Aarg,
                                              const float* __restrict__ W,
                                              const float* __restrict__ bias,
                                              float* __restrict__ Carg,
                                              int M, int Nout) {
    const float* A = (SRC == 0) ? Aarg : (SRC == 1 ? g_h1 : g_h2);
    float* Cp = (DST == 0) ? Carg
              : (DST == 1) ? g_xl1
              : (DST == 2) ? g_xr1
              : (DST == 3) ? g_xl2 : g_xr2;

    __shared__ float As[16][64];
    __shared__ float Bs[16][64];

    int tid = threadIdx.x;
    int bm = blockIdx.x * 64, bn = blockIdx.y * 64;
    int tx = tid & 15, ty = tid >> 4;
    int ar = tid >> 2, ac = tid & 3;    // A tile load coords
    int br = tid >> 4, bc = tid & 15;   // B tile load coords

    float acc[4][4] = {};

#pragma unroll
    for (int k0 = 0; k0 < K; k0 += 16) {
        int arow = bm + ar;
        if (arow >= M) arow = M - 1;
        float4 av = *(const float4*)(A + (size_t)arow * K + k0 + ac * 4);
        As[ac * 4 + 0][ar] = av.x;
        As[ac * 4 + 1][ar] = av.y;
        As[ac * 4 + 2][ar] = av.z;
        As[ac * 4 + 3][ar] = av.w;
        float4 bv = *(const float4*)(W + (size_t)(k0 + br) * Nout + bn + bc * 4);
        *(float4*)&Bs[br][bc * 4] = bv;
        __syncthreads();
#pragma unroll
        for (int k = 0; k < 16; k++) {
            float4 a4 = *(const float4*)&As[k][ty * 4];
            float4 b4 = *(const float4*)&Bs[k][tx * 4];
            float a[4] = {a4.x, a4.y, a4.z, a4.w};
            float b[4] = {b4.x, b4.y, b4.z, b4.w};
#pragma unroll
            for (int i = 0; i < 4; i++)
#pragma unroll
                for (int j = 0; j < 4; j++) acc[i][j] += a[i] * b[j];
        }
        __syncthreads();
    }

#pragma unroll
    for (int i = 0; i < 4; i++) {
        int row = bm + ty * 4 + i;
        if (row >= M) continue;
#pragma unroll
        for (int j = 0; j < 4; j++) {
            int col = bn + tx * 4 + j;
            float v = acc[i][j] + bias[col];
            if (ACT == 1) v = elu1(v);
            Cp[(size_t)row * Nout + col] = v;
        }
    }
}

// ------------------------- edge pass 1: logits + segment max -------------------------
// one warp per edge; lane covers CPT = H*C/32 consecutive channels
template <int LAYER, int H, int C>
__global__ void k_logits(const float* __restrict__ att, int Etot) {
    const int HC  = H * C;
    const int CPT = HC / 32;       // 4 (L1), 2 (L2)
    const int LPH = C / CPT;       // lanes per head: 4 (L1), 32 (L2)
    const float* xl = (LAYER == 1) ? g_xl1 : g_xl2;
    const float* xr = (LAYER == 1) ? g_xr1 : g_xr2;

    int lane = threadIdx.x & 31;
    int e = (blockIdx.x * blockDim.x + threadIdx.x) >> 5;
    if (e >= Etot) return;

    float attr[CPT];
#pragma unroll
    for (int i = 0; i < CPT; i++) attr[i] = att[lane * CPT + i];

    int s = g_src[e], d = g_dst[e];
    const float* pl = xl + (size_t)s * HC + lane * CPT;
    const float* pr = xr + (size_t)d * HC + lane * CPT;

    float v[CPT], u[CPT];
    if (CPT == 4) {
        float4 a = *(const float4*)pl; v[0] = a.x; v[1] = a.y; v[2] = a.z; v[3] = a.w;
        float4 b = *(const float4*)pr; u[0] = b.x; u[1] = b.y; u[2] = b.z; u[3] = b.w;
    } else {
        float2 a = *(const float2*)pl; v[0] = a.x; v[1] = a.y;
        float2 b = *(const float2*)pr; u[0] = b.x; u[1] = b.y;
    }

    float part = 0.f;
#pragma unroll
    for (int i = 0; i < CPT; i++) {
        float z = v[i] + u[i];
        z = (z > 0.f) ? z : 0.2f * z;   // LeakyReLU(0.2)
        part += attr[i] * z;
    }
#pragma unroll
    for (int off = 1; off < LPH; off <<= 1)
        part += __shfl_xor_sync(0xffffffffu, part, off);

    if ((lane & (LPH - 1)) == 0) {
        int h = lane / LPH;
        g_ex[(size_t)e * H + h] = part;
        atomicMax(&g_mu[(size_t)d * H + h], ford(part));
    }
}

// ------------------------- edge pass 2: exp + segment sum -------------------------
template <int H>
__global__ void k_soft(int Etot) {
    int i = blockIdx.x * blockDim.x + threadIdx.x;
    if (i >= Etot * H) return;
    int e = i / H;
    int h = i - e * H;
    int d = g_dst[e];
    float m = funord(g_mu[(size_t)d * H + h]);
    float ex = expf(g_ex[i] - m);
    g_ex[i] = ex;
    atomicAdd(&g_den[(size_t)d * H + h], ex);
}

// ------------------------- edge pass 3: alpha-weighted scatter add -------------------------
template <int LAYER, int H, int C>
__global__ void k_aggr(int Etot) {
    const int HC  = H * C;
    const int CPT = HC / 32;
    const int LPH = C / CPT;
    const float* xl = (LAYER == 1) ? g_xl1 : g_xl2;
    float* agg = (LAYER == 1) ? g_agg1 : g_agg2;

    int lane = threadIdx.x & 31;
    int e = (blockIdx.x * blockDim.x + threadIdx.x) >> 5;
    if (e >= Etot) return;

    int s = g_src[e], d = g_dst[e];
    int h = lane / LPH;
    float alpha = g_ex[(size_t)e * H + h] / g_den[(size_t)d * H + h];

    const float* pl = xl + (size_t)s * HC + lane * CPT;
    float* po = agg + (size_t)d * HC + lane * CPT;

    if (CPT == 4) {
        float4 a = *(const float4*)pl;
        atomicAdd((float4*)po, make_float4(a.x * alpha, a.y * alpha, a.z * alpha, a.w * alpha));
    } else {
        float2 a = *(const float2*)pl;
        atomicAdd((float2*)po, make_float2(a.x * alpha, a.y * alpha));
    }
}

// ------------------------- bias + ELU per layer -------------------------
template <int LAYER>
__global__ void k_bias_elu(const float* __restrict__ bias, int N) {
    const int HC = (LAYER == 1) ? 128 : 64;
    const float* agg = (LAYER == 1) ? g_agg1 : g_agg2;
    float* h = (LAYER == 1) ? g_h1 : g_h2;
    int i = blockIdx.x * blockDim.x + threadIdx.x;
    if (i < N * HC) {
        float v = agg[i] + bias[i & (HC - 1)];
        h[i] = elu1(v);
    }
}

// ------------------------- launch -------------------------
static inline int cdiv(int a, int b) { return (a + b - 1) / b; }

extern "C" void kernel_launch(void* const* d_in, const int* in_sizes, int n_in,
                              void* d_out, int out_size) {
    const float* x     = (const float*)d_in[0];
    const int*   ei    = (const int*)d_in[1];
    const float* Wl1   = (const float*)d_in[2];
    const float* bl1   = (const float*)d_in[3];
    const float* Wr1   = (const float*)d_in[4];
    const float* br1   = (const float*)d_in[5];
    const float* att1  = (const float*)d_in[6];
    const float* bias1 = (const float*)d_in[7];
    const float* Wl2   = (const float*)d_in[8];
    const float* bl2   = (const float*)d_in[9];
    const float* Wr2   = (const float*)d_in[10];
    const float* br2   = (const float*)d_in[11];
    const float* att2  = (const float*)d_in[12];
    const float* bias2 = (const float*)d_in[13];
    const float* Wlin  = (const float*)d_in[14];
    const float* blin  = (const float*)d_in[15];

    int N = in_sizes[0] / 128;
    int E = in_sizes[1] / 2;
    int Etot = E + N;

    k_edges<<<cdiv(Etot, 256), 256>>>(ei, E, N);

    // ---- layer 1: GATv2 (H=8, C=16, concat) ----
    dim3 g1(cdiv(N, 64), 2);
    k_gemm<128, 0, 0, 1><<<g1, 256>>>(x, Wl1, bl1, nullptr, N, 128);
    k_gemm<128, 0, 0, 2><<<g1, 256>>>(x, Wr1, br1, nullptr, N, 128);
    k_zero<1><<<cdiv(N * 128, 256), 256>>>(N);
    k_logits<1, 8, 16><<<cdiv(Etot * 32, 256), 256>>>(att1, Etot);
    k_soft<8><<<cdiv(Etot * 8, 256), 256>>>(Etot);
    k_aggr<1, 8, 16><<<cdiv(Etot * 32, 256), 256>>>(Etot);
    k_bias_elu<1><<<cdiv(N * 128, 256), 256>>>(bias1, N);

    // ---- layer 2: GATv2 (H=1, C=64) ----
    dim3 g2(cdiv(N, 64), 1);
    k_gemm<128, 0, 1, 3><<<g2, 256>>>(nullptr, Wl2, bl2, nullptr, N, 64);
    k_gemm<128, 0, 1, 4><<<g2, 256>>>(nullptr, Wr2, br2, nullptr, N, 64);
    k_zero<2><<<cdiv(N * 64, 256), 256>>>(N);
    k_logits<2, 1, 64><<<cdiv(Etot * 32, 256), 256>>>(att2, Etot);
    k_soft<1><<<cdiv(Etot, 256), 256>>>(Etot);
    k_aggr<2, 1, 64><<<cdiv(Etot * 32, 256), 256>>>(Etot);
    k_bias_elu<2><<<cdiv(N * 64, 256), 256>>>(bias2, N);

    // ---- final linear + ELU -> d_out [N,128] ----
    dim3 g3(cdiv(N, 64), 2);
    k_gemm<64, 1, 2, 0><<<g3, 256>>>(nullptr, Wlin, blin, (float*)d_out, N, 128);
}

// round 3
// speedup vs baseline: 1.0789x; 1.0789x over previous
#include <cuda_runtime.h>

#define NMAX    50048
#define EMAX    800000
#define ETOTMAX (NMAX + EMAX)

// ------------------------- scratch (device globals) -------------------------
__device__ __align__(16) float    g_xl1[NMAX * 128];
__device__ __align__(16) float    g_xr1[NMAX * 128];
__device__ __align__(16) float    g_agg1[NMAX * 128];
__device__ __align__(16) float    g_h1[NMAX * 128];
__device__ __align__(16) float    g_xl2[NMAX * 64];
__device__ __align__(16) float    g_xr2[NMAX * 64];
__device__ __align__(16) float    g_agg2[NMAX * 64];
__device__ __align__(16) float    g_h2[NMAX * 64];
__device__ __align__(16) float    g_lg[(size_t)ETOTMAX * 8];  // per-edge logits
__device__ __align__(16) unsigned g_mu1[NMAX * 8];
__device__ __align__(16) float    g_den1[NMAX * 8];
__device__ __align__(16) unsigned g_mu2[NMAX];
__device__ __align__(16) float    g_den2[NMAX];
__device__ __align__(16) int      g_src[ETOTMAX];
__device__ __align__(16) int      g_dst[ETOTMAX];

// ------------------------- helpers -------------------------
__device__ __forceinline__ unsigned ford(float f) {
    unsigned u = __float_as_uint(f);
    return (u & 0x80000000u) ? ~u : (u | 0x80000000u);
}
__device__ __forceinline__ float funord(unsigned u) {
    return (u & 0x80000000u) ? __uint_as_float(u ^ 0x80000000u) : __uint_as_float(~u);
}
__device__ __forceinline__ float elu1(float v) { return v > 0.f ? v : expm1f(v); }

// ------------------------- edge index copy (+ self loops) -------------------------
__global__ void k_edges(const int* __restrict__ ei, int E, int N) {
    int i = blockIdx.x * blockDim.x + threadIdx.x;
    int tot = E + N;
    if (i < tot) {
        if (i < E) {
            g_src[i] = ei[i];
            g_dst[i] = ei[E + i];
        } else {
            g_src[i] = i - E;
            g_dst[i] = i - E;
        }
    }
}

// ------------------------- single upfront init (both layers) -------------------------
__global__ void k_init(int N) {
    int i = blockIdx.x * blockDim.x + threadIdx.x;
    if (i < N * 128) g_agg1[i] = 0.f;
    if (i < N * 64)  g_agg2[i] = 0.f;
    if (i < N * 8) { g_mu1[i] = 0u; g_den1[i] = 0.f; }
    if (i < N)     { g_mu2[i] = 0u; g_den2[i] = 0.f; }
}

// ------------------------- SGEMM: 128xBN tile, 256 thr, 8x(BN/16) microtile --------------
// SRC: 0 = Aarg, 1 = g_h1, 2 = g_h2.
// DSTSEL: 0 = Carg (ldc=BN), 1 = y-select (xl1,xr1) ldc=128, 2 = y-select (xl2,xr2) ldc=64.
// For DSTSEL 1/2, blockIdx.y selects W0/b0 (y=0) or W1/b1 (y=1); W is K x BN row-major.
template <int K, int BN, int ACT, int SRC, int DSTSEL>
__global__ __launch_bounds__(256) void k_gemm(const float* __restrict__ Aarg,
                                              const float* __restrict__ W0,
                                              const float* __restrict__ W1,
                                              const float* __restrict__ b0,
                                              const float* __restrict__ b1,
                                              float* __restrict__ Carg, int M) {
    const int MN = BN / 16;          // 8 or 4
    const int NG = MN / 4;           // 2 or 1 column groups of 4
    const float* A = (SRC == 0) ? Aarg : (SRC == 1 ? g_h1 : g_h2);
    const float* W    = (blockIdx.y == 0) ? W0 : W1;
    const float* bias = (blockIdx.y == 0) ? b0 : b1;
    float* C;
    int ldc;
    if (DSTSEL == 0)      { C = Carg; ldc = BN; }
    else if (DSTSEL == 1) { C = (blockIdx.y == 0) ? g_xl1 : g_xr1; ldc = 128; }
    else                  { C = (blockIdx.y == 0) ? g_xl2 : g_xr2; ldc = 64; }

    __shared__ float As[16][128];
    __shared__ float Bs[16][BN];

    int tid = threadIdx.x;
    int bm = blockIdx.x * 128;
    int tx = tid & 15, ty = tid >> 4;

    float acc[8][MN] = {};

#pragma unroll 1
    for (int k0 = 0; k0 < K; k0 += 16) {
        // A tile: 128 rows x 16 k, transposed into As[k][row]
        {
            int row = tid >> 1;
            int arow = bm + row; if (arow >= M) arow = M - 1;
#pragma unroll
            for (int r = 0; r < 2; r++) {
                int cq = (tid & 1) * 2 + r;
                float4 v = *(const float4*)(A + (size_t)arow * K + k0 + cq * 4);
                As[cq * 4 + 0][row] = v.x;
                As[cq * 4 + 1][row] = v.y;
                As[cq * 4 + 2][row] = v.z;
                As[cq * 4 + 3][row] = v.w;
            }
        }
        // B tile: 16 rows x BN, direct copy
        {
            const int NF4 = BN / 4;
#pragma unroll
            for (int q = tid; q < 16 * NF4; q += 256) {
                int row = q / NF4, cf = q % NF4;
                *(float4*)&Bs[row][cf * 4] =
                    *(const float4*)(W + (size_t)(k0 + row) * BN + cf * 4);
            }
        }
        __syncthreads();
#pragma unroll
        for (int k = 0; k < 16; k++) {
            float a[8], b[MN];
            *(float4*)&a[0] = *(const float4*)&As[k][ty * 8];
            *(float4*)&a[4] = *(const float4*)&As[k][ty * 8 + 4];
#pragma unroll
            for (int g = 0; g < NG; g++)
                *(float4*)&b[g * 4] = *(const float4*)&Bs[k][g * 64 + tx * 4];
#pragma unroll
            for (int i = 0; i < 8; i++)
#pragma unroll
                for (int j = 0; j < MN; j++) acc[i][j] += a[i] * b[j];
        }
        __syncthreads();
    }

#pragma unroll
    for (int i = 0; i < 8; i++) {
        int row = bm + ty * 8 + i;
        if (row >= M) continue;
#pragma unroll
        for (int g = 0; g < NG; g++) {
            int col = g * 64 + tx * 4;
            float4 v;
            v.x = acc[i][g * 4 + 0] + bias[col + 0];
            v.y = acc[i][g * 4 + 1] + bias[col + 1];
            v.z = acc[i][g * 4 + 2] + bias[col + 2];
            v.w = acc[i][g * 4 + 3] + bias[col + 3];
            if (ACT) { v.x = elu1(v.x); v.y = elu1(v.y); v.z = elu1(v.z); v.w = elu1(v.w); }
            *(float4*)(C + (size_t)row * ldc + col) = v;
        }
    }
}

// ------------------------- edge pass 1: logits + segment max -------------------------
template <int LAYER, int H, int C>
__global__ void k_logits(const float* __restrict__ att, int Etot) {
    const int HC  = H * C;
    const int CPT = HC / 32;       // 4 (L1), 2 (L2)
    const int LPH = C / CPT;       // lanes per head: 4 (L1), 32 (L2)
    const float* xl = (LAYER == 1) ? g_xl1 : g_xl2;
    const float* xr = (LAYER == 1) ? g_xr1 : g_xr2;
    unsigned* mu = (LAYER == 1) ? g_mu1 : g_mu2;

    int lane = threadIdx.x & 31;
    int e = (blockIdx.x * blockDim.x + threadIdx.x) >> 5;
    if (e >= Etot) return;

    float attr[CPT];
#pragma unroll
    for (int i = 0; i < CPT; i++) attr[i] = att[lane * CPT + i];

    int s = g_src[e], d = g_dst[e];
    const float* pl = xl + (size_t)s * HC + lane * CPT;
    const float* pr = xr + (size_t)d * HC + lane * CPT;

    float v[CPT], u[CPT];
    if (CPT == 4) {
        float4 a = *(const float4*)pl; v[0] = a.x; v[1] = a.y; v[2] = a.z; v[3] = a.w;
        float4 b = *(const float4*)pr; u[0] = b.x; u[1] = b.y; u[2] = b.z; u[3] = b.w;
    } else {
        float2 a = *(const float2*)pl; v[0] = a.x; v[1] = a.y;
        float2 b = *(const float2*)pr; u[0] = b.x; u[1] = b.y;
    }

    float part = 0.f;
#pragma unroll
    for (int i = 0; i < CPT; i++) {
        float z = v[i] + u[i];
        z = (z > 0.f) ? z : 0.2f * z;   // LeakyReLU(0.2)
        part += attr[i] * z;
    }
#pragma unroll
    for (int off = 1; off < LPH; off <<= 1)
        part += __shfl_xor_sync(0xffffffffu, part, off);

    if ((lane & (LPH - 1)) == 0) {
        int h = lane / LPH;
        g_lg[(size_t)e * H + h] = part;
        atomicMax(&mu[(size_t)d * H + h], ford(part));
    }
}

// ---------- edge pass 2 (fused): exp + den accumulate + unnormalized scatter add ----------
template <int LAYER, int H, int C>
__global__ void k_aggr(int Etot) {
    const int HC  = H * C;
    const int CPT = HC / 32;
    const int LPH = C / CPT;
    const float* xl = (LAYER == 1) ? g_xl1 : g_xl2;
    float* agg = (LAYER == 1) ? g_agg1 : g_agg2;
    const unsigned* mu = (LAYER == 1) ? g_mu1 : g_mu2;
    float* den = (LAYER == 1) ? g_den1 : g_den2;

    int lane = threadIdx.x & 31;
    int e = (blockIdx.x * blockDim.x + threadIdx.x) >> 5;
    if (e >= Etot) return;

    int s = g_src[e], d = g_dst[e];
    int h = lane / LPH;
    float logit = g_lg[(size_t)e * H + h];
    float m = funord(mu[(size_t)d * H + h]);
    float ex = expf(logit - m);

    if ((lane & (LPH - 1)) == 0) atomicAdd(&den[(size_t)d * H + h], ex);

    const float* pl = xl + (size_t)s * HC + lane * CPT;
    float* po = agg + (size_t)d * HC + lane * CPT;

    if (CPT == 4) {
        float4 a = *(const float4*)pl;
        atomicAdd((float4*)po, make_float4(a.x * ex, a.y * ex, a.z * ex, a.w * ex));
    } else {
        float2 a = *(const float2*)pl;
        atomicAdd((float2*)po, make_float2(a.x * ex, a.y * ex));
    }
}

// ------------------------- normalize + bias + ELU per layer -------------------------
template <int LAYER>
__global__ void k_norm_elu(const float* __restrict__ bias, int N) {
    const int HC = (LAYER == 1) ? 128 : 64;
    const int C  = (LAYER == 1) ? 16 : 64;
    const int H  = (LAYER == 1) ? 8 : 1;
    const float* agg = (LAYER == 1) ? g_agg1 : g_agg2;
    const float* den = (LAYER == 1) ? g_den1 : g_den2;
    float* out = (LAYER == 1) ? g_h1 : g_h2;
    int i = blockIdx.x * blockDim.x + threadIdx.x;
    if (i < N * HC) {
        int n = i / HC;
        int c = i & (HC - 1);
        int h = c / C;
        float v = agg[i] / den[(size_t)n * H + h] + bias[c];
        out[i] = elu1(v);
    }
}

// ------------------------- launch -------------------------
static inline int cdiv(int a, int b) { return (a + b - 1) / b; }

extern "C" void kernel_launch(void* const* d_in, const int* in_sizes, int n_in,
                              void* d_out, int out_size) {
    const float* x     = (const float*)d_in[0];
    const int*   ei    = (const int*)d_in[1];
    const float* Wl1   = (const float*)d_in[2];
    const float* bl1   = (const float*)d_in[3];
    const float* Wr1   = (const float*)d_in[4];
    const float* br1   = (const float*)d_in[5];
    const float* att1  = (const float*)d_in[6];
    const float* bias1 = (const float*)d_in[7];
    const float* Wl2   = (const float*)d_in[8];
    const float* bl2   = (const float*)d_in[9];
    const float* Wr2   = (const float*)d_in[10];
    const float* br2   = (const float*)d_in[11];
    const float* att2  = (const float*)d_in[12];
    const float* bias2 = (const float*)d_in[13];
    const float* Wlin  = (const float*)d_in[14];
    const float* blin  = (const float*)d_in[15];

    int N = in_sizes[0] / 128;
    int E = in_sizes[1] / 2;
    int Etot = E + N;

    k_edges<<<cdiv(Etot, 256), 256>>>(ei, E, N);
    k_init<<<cdiv(N * 128, 256), 256>>>(N);

    // ---- layer 1: GATv2 (H=8, C=16, concat): fused dual GEMM ----
    dim3 g1(cdiv(N, 128), 2);
    k_gemm<128, 128, 0, 0, 1><<<g1, 256>>>(x, Wl1, Wr1, bl1, br1, nullptr, N);
    k_logits<1, 8, 16><<<cdiv(Etot * 32, 256), 256>>>(att1, Etot);
    k_aggr<1, 8, 16><<<cdiv(Etot * 32, 256), 256>>>(Etot);
    k_norm_elu<1><<<cdiv(N * 128, 256), 256>>>(bias1, N);

    // ---- layer 2: GATv2 (H=1, C=64): fused dual GEMM ----
    dim3 g2(cdiv(N, 128), 2);
    k_gemm<128, 64, 0, 1, 2><<<g2, 256>>>(nullptr, Wl2, Wr2, bl2, br2, nullptr, N);
    k_logits<2, 1, 64><<<cdiv(Etot * 32, 256), 256>>>(att2, Etot);
    k_aggr<2, 1, 64><<<cdiv(Etot * 32, 256), 256>>>(Etot);
    k_norm_elu<2><<<cdiv(N * 64, 256), 256>>>(bias2, N);

    // ---- final linear + ELU -> d_out [N,128] ----
    dim3 g3(cdiv(N, 128), 1);
    k_gemm<64, 128, 1, 2, 0><<<g3, 256>>>(nullptr, Wlin, Wlin, blin, blin, (float*)d_out, N);
}

// round 4
// speedup vs baseline: 1.7308x; 1.6042x over previous
#include <cuda_runtime.h>

#define NMAX    50048
#define EMAX    800000
#define ETOTMAX (NMAX + EMAX)

// ------------------------- scratch (device globals) -------------------------
__device__ __align__(16) float g_xl1[NMAX * 128];
__device__ __align__(16) float g_xr1[NMAX * 128];
__device__ __align__(16) float g_agg1[NMAX * 128];
__device__ __align__(16) float g_h1[NMAX * 128];
__device__ __align__(16) float g_xl2[NMAX * 64];
__device__ __align__(16) float g_xr2[NMAX * 64];
__device__ __align__(16) float g_agg2[NMAX * 64];
__device__ __align__(16) float g_h2[NMAX * 64];
__device__ __align__(16) float g_den1[NMAX * 8];
__device__ __align__(16) float g_den2[NMAX];
__device__ __align__(16) int   g_src[ETOTMAX];
__device__ __align__(16) int   g_dst[ETOTMAX];

// ------------------------- helpers -------------------------
__device__ __forceinline__ float elu1(float v) { return v > 0.f ? v : expm1f(v); }

// ------------------------- edge index copy (+ self loops) -------------------------
__global__ void k_edges(const int* __restrict__ ei, int E, int N) {
    int i = blockIdx.x * blockDim.x + threadIdx.x;
    int tot = E + N;
    if (i < tot) {
        if (i < E) {
            g_src[i] = ei[i];
            g_dst[i] = ei[E + i];
        } else {
            g_src[i] = i - E;
            g_dst[i] = i - E;
        }
    }
}

// ------------------------- single upfront init (both layers) -------------------------
__global__ void k_init(int N) {
    int i = blockIdx.x * blockDim.x + threadIdx.x;
    if (i < N * 128) g_agg1[i] = 0.f;
    if (i < N * 64)  g_agg2[i] = 0.f;
    if (i < N * 8)   g_den1[i] = 0.f;
    if (i < N)       g_den2[i] = 0.f;
}

// ------------------------- SGEMM: 128xBN tile, 256 thr, 8x(BN/16) microtile --------------
// SRC: 0 = Aarg, 1 = g_h1, 2 = g_h2.
// DSTSEL: 0 = Carg (ldc=BN), 1 = y-select (xl1,xr1) ldc=128, 2 = y-select (xl2,xr2) ldc=64.
template <int K, int BN, int ACT, int SRC, int DSTSEL>
__global__ __launch_bounds__(256) void k_gemm(const float* __restrict__ Aarg,
                                              const float* __restrict__ W0,
                                              const float* __restrict__ W1,
                                              const float* __restrict__ b0,
                                              const float* __restrict__ b1,
                                              float* __restrict__ Carg, int M) {
    const int MN = BN / 16;          // 8 or 4
    const int NG = MN / 4;           // 2 or 1 column groups of 4
    const float* A = (SRC == 0) ? Aarg : (SRC == 1 ? g_h1 : g_h2);
    const float* W    = (blockIdx.y == 0) ? W0 : W1;
    const float* bias = (blockIdx.y == 0) ? b0 : b1;
    float* C;
    int ldc;
    if (DSTSEL == 0)      { C = Carg; ldc = BN; }
    else if (DSTSEL == 1) { C = (blockIdx.y == 0) ? g_xl1 : g_xr1; ldc = 128; }
    else                  { C = (blockIdx.y == 0) ? g_xl2 : g_xr2; ldc = 64; }

    __shared__ float As[16][128];
    __shared__ float Bs[16][BN];

    int tid = threadIdx.x;
    int bm = blockIdx.x * 128;
    int tx = tid & 15, ty = tid >> 4;

    float acc[8][MN] = {};

#pragma unroll 1
    for (int k0 = 0; k0 < K; k0 += 16) {
        {
            int row = tid >> 1;
            int arow = bm + row; if (arow >= M) arow = M - 1;
#pragma unroll
            for (int r = 0; r < 2; r++) {
                int cq = (tid & 1) * 2 + r;
                float4 v = *(const float4*)(A + (size_t)arow * K + k0 + cq * 4);
                As[cq * 4 + 0][row] = v.x;
                As[cq * 4 + 1][row] = v.y;
                As[cq * 4 + 2][row] = v.z;
                As[cq * 4 + 3][row] = v.w;
            }
        }
        {
            const int NF4 = BN / 4;
#pragma unroll
            for (int q = tid; q < 16 * NF4; q += 256) {
                int row = q / NF4, cf = q % NF4;
                *(float4*)&Bs[row][cf * 4] =
                    *(const float4*)(W + (size_t)(k0 + row) * BN + cf * 4);
            }
        }
        __syncthreads();
#pragma unroll
        for (int k = 0; k < 16; k++) {
            float a[8], b[MN];
            *(float4*)&a[0] = *(const float4*)&As[k][ty * 8];
            *(float4*)&a[4] = *(const float4*)&As[k][ty * 8 + 4];
#pragma unroll
            for (int g = 0; g < NG; g++)
                *(float4*)&b[g * 4] = *(const float4*)&Bs[k][g * 64 + tx * 4];
#pragma unroll
            for (int i = 0; i < 8; i++)
#pragma unroll
                for (int j = 0; j < MN; j++) acc[i][j] += a[i] * b[j];
        }
        __syncthreads();
    }

#pragma unroll
    for (int i = 0; i < 8; i++) {
        int row = bm + ty * 8 + i;
        if (row >= M) continue;
#pragma unroll
        for (int g = 0; g < NG; g++) {
            int col = g * 64 + tx * 4;
            float4 v;
            v.x = acc[i][g * 4 + 0] + bias[col + 0];
            v.y = acc[i][g * 4 + 1] + bias[col + 1];
            v.z = acc[i][g * 4 + 2] + bias[col + 2];
            v.w = acc[i][g * 4 + 3] + bias[col + 3];
            if (ACT) { v.x = elu1(v.x); v.y = elu1(v.y); v.z = elu1(v.z); v.w = elu1(v.w); }
            *(float4*)(C + (size_t)row * ldc + col) = v;
        }
    }
}

// ------------- FUSED edge pass, layer 1 (H=8, C=16): one warp per edge -------------
// Softmax computed unshifted (shift-invariant; logits are O(10) « 88, self-loops keep den>0).
__global__ void k_edge1(const float* __restrict__ att, int Etot) {
    int lane = threadIdx.x & 31;
    int e = (blockIdx.x * blockDim.x + threadIdx.x) >> 5;
    if (e >= Etot) return;

    float4 attr = *(const float4*)(att + lane * 4);

    int s = g_src[e], d = g_dst[e];
    float4 a = *(const float4*)(g_xl1 + (size_t)s * 128 + lane * 4);
    float4 b = *(const float4*)(g_xr1 + (size_t)d * 128 + lane * 4);

    float z0 = a.x + b.x; z0 = z0 > 0.f ? z0 : 0.2f * z0;
    float z1 = a.y + b.y; z1 = z1 > 0.f ? z1 : 0.2f * z1;
    float z2 = a.z + b.z; z2 = z2 > 0.f ? z2 : 0.2f * z2;
    float z3 = a.w + b.w; z3 = z3 > 0.f ? z3 : 0.2f * z3;
    float part = attr.x * z0 + attr.y * z1 + attr.z * z2 + attr.w * z3;

    // butterfly over the 4 lanes of this head -> all lanes hold head sum
    part += __shfl_xor_sync(0xffffffffu, part, 1);
    part += __shfl_xor_sync(0xffffffffu, part, 2);

    float ex = expf(part);
    if ((lane & 3) == 0) atomicAdd(&g_den1[(size_t)d * 8 + (lane >> 2)], ex);

    atomicAdd((float4*)(g_agg1 + (size_t)d * 128 + lane * 4),
              make_float4(a.x * ex, a.y * ex, a.z * ex, a.w * ex));
}

// ------------- FUSED edge pass, layer 2 (H=1, C=64): 16 lanes per edge -------------
__global__ void k_edge2(const float* __restrict__ att, int Etot) {
    int gtid = blockIdx.x * blockDim.x + threadIdx.x;
    int sl = gtid & 15;
    int e = gtid >> 4;
    if (e >= Etot) return;

    float4 attr = *(const float4*)(att + sl * 4);

    int s = g_src[e], d = g_dst[e];
    float4 a = *(const float4*)(g_xl2 + (size_t)s * 64 + sl * 4);
    float4 b = *(const float4*)(g_xr2 + (size_t)d * 64 + sl * 4);

    float z0 = a.x + b.x; z0 = z0 > 0.f ? z0 : 0.2f * z0;
    float z1 = a.y + b.y; z1 = z1 > 0.f ? z1 : 0.2f * z1;
    float z2 = a.z + b.z; z2 = z2 > 0.f ? z2 : 0.2f * z2;
    float z3 = a.w + b.w; z3 = z3 > 0.f ? z3 : 0.2f * z3;
    float part = attr.x * z0 + attr.y * z1 + attr.z * z2 + attr.w * z3;

    // butterfly within the 16-lane group
    part += __shfl_xor_sync(0xffffffffu, part, 1);
    part += __shfl_xor_sync(0xffffffffu, part, 2);
    part += __shfl_xor_sync(0xffffffffu, part, 4);
    part += __shfl_xor_sync(0xffffffffu, part, 8);

    float ex = expf(part);
    if (sl == 0) atomicAdd(&g_den2[d], ex);

    atomicAdd((float4*)(g_agg2 + (size_t)d * 64 + sl * 4),
              make_float4(a.x * ex, a.y * ex, a.z * ex, a.w * ex));
}

// ------------------------- normalize + bias + ELU per layer -------------------------
template <int LAYER>
__global__ void k_norm_elu(const float* __restrict__ bias, int N) {
    const int HC = (LAYER == 1) ? 128 : 64;
    const int C  = (LAYER == 1) ? 16 : 64;
    const int H  = (LAYER == 1) ? 8 : 1;
    const float* agg = (LAYER == 1) ? g_agg1 : g_agg2;
    const float* den = (LAYER == 1) ? g_den1 : g_den2;
    float* out = (LAYER == 1) ? g_h1 : g_h2;
    int i = blockIdx.x * blockDim.x + threadIdx.x;
    if (i < N * HC) {
        int n = i / HC;
        int c = i & (HC - 1);
        int h = c / C;
        float v = agg[i] / den[(size_t)n * H + h] + bias[c];
        out[i] = elu1(v);
    }
}

// ------------------------- launch -------------------------
static inline int cdiv(int a, int b) { return (a + b - 1) / b; }

extern "C" void kernel_launch(void* const* d_in, const int* in_sizes, int n_in,
                              void* d_out, int out_size) {
    const float* x     = (const float*)d_in[0];
    const int*   ei    = (const int*)d_in[1];
    const float* Wl1   = (const float*)d_in[2];
    const float* bl1   = (const float*)d_in[3];
    const float* Wr1   = (const float*)d_in[4];
    const float* br1   = (const float*)d_in[5];
    const float* att1  = (const float*)d_in[6];
    const float* bias1 = (const float*)d_in[7];
    const float* Wl2   = (const float*)d_in[8];
    const float* bl2   = (const float*)d_in[9];
    const float* Wr2   = (const float*)d_in[10];
    const float* br2   = (const float*)d_in[11];
    const float* att2  = (const float*)d_in[12];
    const float* bias2 = (const float*)d_in[13];
    const float* Wlin  = (const float*)d_in[14];
    const float* blin  = (const float*)d_in[15];

    int N = in_sizes[0] / 128;
    int E = in_sizes[1] / 2;
    int Etot = E + N;

    k_edges<<<cdiv(Etot, 256), 256>>>(ei, E, N);
    k_init<<<cdiv(N * 128, 256), 256>>>(N);

    // ---- layer 1: GATv2 (H=8, C=16, concat) ----
    dim3 g1(cdiv(N, 128), 2);
    k_gemm<128, 128, 0, 0, 1><<<g1, 256>>>(x, Wl1, Wr1, bl1, br1, nullptr, N);
    k_edge1<<<cdiv(Etot * 32, 256), 256>>>(att1, Etot);
    k_norm_elu<1><<<cdiv(N * 128, 256), 256>>>(bias1, N);

    // ---- layer 2: GATv2 (H=1, C=64) ----
    dim3 g2(cdiv(N, 128), 2);
    k_gemm<128, 64, 0, 1, 2><<<g2, 256>>>(nullptr, Wl2, Wr2, bl2, br2, nullptr, N);
    k_edge2<<<cdiv(Etot * 16, 256), 256>>>(att2, Etot);
    k_norm_elu<2><<<cdiv(N * 64, 256), 256>>>(bias2, N);

    // ---- final linear + ELU -> d_out [N,128] ----
    dim3 g3(cdiv(N, 128), 1);
    k_gemm<64, 128, 1, 2, 0><<<g3, 256>>>(nullptr, Wlin, Wlin, blin, blin, (float*)d_out, N);
}

// round 5
// speedup vs baseline: 2.2912x; 1.3238x over previous
#include <cuda_runtime.h>

#define NMAX    50048
#define EMAX    800000
#define ETOTMAX (NMAX + EMAX)
#define NBLKMAX 256

// ------------------------- scratch (device globals) -------------------------
__device__ __align__(16) float g_xl1[NMAX * 128];
__device__ __align__(16) float g_xr1[NMAX * 128];
__device__ __align__(16) float g_h1[NMAX * 128];
__device__ __align__(16) float g_xl2[NMAX * 64];
__device__ __align__(16) float g_xr2[NMAX * 64];
__device__ __align__(16) float g_h2[NMAX * 64];
__device__ __align__(16) int   g_deg[NMAX];
__device__ __align__(16) int   g_pre[NMAX];
__device__ __align__(16) int   g_bsum[NBLKMAX];
__device__ __align__(16) int   g_rowptr[NMAX + 1];
__device__ __align__(16) int   g_cursor[NMAX];
__device__ __align__(16) int   g_esrc[ETOTMAX];

// ------------------------- helpers -------------------------
__device__ __forceinline__ float elu1(float v) { return v > 0.f ? v : expm1f(v); }

// ------------------------- CSR build -------------------------
__global__ void k_initdeg(int N) {
    int i = blockIdx.x * blockDim.x + threadIdx.x;
    if (i < N) g_deg[i] = 1;              // self-loop
}
__global__ void k_hist(const int* __restrict__ ei, int E) {
    int i = blockIdx.x * blockDim.x + threadIdx.x;
    if (i < E) atomicAdd(&g_deg[ei[E + i]], 1);
}
__global__ void k_scanblk(int N) {
    __shared__ int sh[256];
    int i = blockIdx.x * 256 + threadIdx.x;
    int v = (i < N) ? g_deg[i] : 0;
    sh[threadIdx.x] = v;
    __syncthreads();
    for (int off = 1; off < 256; off <<= 1) {
        int t = (threadIdx.x >= off) ? sh[threadIdx.x - off] : 0;
        __syncthreads();
        sh[threadIdx.x] += t;
        __syncthreads();
    }
    if (i < N) g_pre[i] = sh[threadIdx.x] - v;   // exclusive
    if (threadIdx.x == 255) g_bsum[blockIdx.x] = sh[255];
}
__global__ void k_scantop(int NB) {
    __shared__ int sh[256];
    int v = (threadIdx.x < NB) ? g_bsum[threadIdx.x] : 0;
    sh[threadIdx.x] = v;
    __syncthreads();
    for (int off = 1; off < 256; off <<= 1) {
        int t = (threadIdx.x >= off) ? sh[threadIdx.x - off] : 0;
        __syncthreads();
        sh[threadIdx.x] += t;
        __syncthreads();
    }
    if (threadIdx.x < NB) g_bsum[threadIdx.x] = sh[threadIdx.x] - v;  // exclusive
}
__global__ void k_finalize(int N, int Etot) {
    int i = blockIdx.x * blockDim.x + threadIdx.x;
    if (i < N) {
        int rp = g_pre[i] + g_bsum[i >> 8];
        g_rowptr[i] = rp;
        g_cursor[i] = rp + 1;
        g_esrc[rp] = i;                   // self-loop occupies first slot
        if (i == 0) g_rowptr[N] = Etot;
    }
}
__global__ void k_scatter(const int* __restrict__ ei, int E) {
    int i = blockIdx.x * blockDim.x + threadIdx.x;
    if (i < E) {
        int d = ei[E + i];
        int slot = atomicAdd(&g_cursor[d], 1);
        g_esrc[slot] = ei[i];
    }
}

// ------------------------- SGEMM: 128xBN tile, 256 thr --------------
// SRC: 0 = Aarg, 1 = g_h1, 2 = g_h2.
// DSTSEL: 0 = Carg (ldc=BN), 1 = y-select (xl1,xr1) ldc=128, 2 = y-select (xl2,xr2) ldc=64.
template <int K, int BN, int ACT, int SRC, int DSTSEL>
__global__ __launch_bounds__(256) void k_gemm(const float* __restrict__ Aarg,
                                              const float* __restrict__ W0,
                                              const float* __restrict__ W1,
                                              const float* __restrict__ b0,
                                              const float* __restrict__ b1,
                                              float* __restrict__ Carg, int M) {
    const int MN = BN / 16;
    const int NG = MN / 4;
    const float* A = (SRC == 0) ? Aarg : (SRC == 1 ? g_h1 : g_h2);
    const float* W    = (blockIdx.y == 0) ? W0 : W1;
    const float* bias = (blockIdx.y == 0) ? b0 : b1;
    float* C;
    int ldc;
    if (DSTSEL == 0)      { C = Carg; ldc = BN; }
    else if (DSTSEL == 1) { C = (blockIdx.y == 0) ? g_xl1 : g_xr1; ldc = 128; }
    else                  { C = (blockIdx.y == 0) ? g_xl2 : g_xr2; ldc = 64; }

    __shared__ float As[16][128];
    __shared__ float Bs[16][BN];

    int tid = threadIdx.x;
    int bm = blockIdx.x * 128;
    int tx = tid & 15, ty = tid >> 4;

    float acc[8][MN] = {};

#pragma unroll 1
    for (int k0 = 0; k0 < K; k0 += 16) {
        {
            int row = tid >> 1;
            int arow = bm + row; if (arow >= M) arow = M - 1;
#pragma unroll
            for (int r = 0; r < 2; r++) {
                int cq = (tid & 1) * 2 + r;
                float4 v = *(const float4*)(A + (size_t)arow * K + k0 + cq * 4);
                As[cq * 4 + 0][row] = v.x;
                As[cq * 4 + 1][row] = v.y;
                As[cq * 4 + 2][row] = v.z;
                As[cq * 4 + 3][row] = v.w;
            }
        }
        {
            const int NF4 = BN / 4;
#pragma unroll
            for (int q = tid; q < 16 * NF4; q += 256) {
                int row = q / NF4, cf = q % NF4;
                *(float4*)&Bs[row][cf * 4] =
                    *(const float4*)(W + (size_t)(k0 + row) * BN + cf * 4);
            }
        }
        __syncthreads();
#pragma unroll
        for (int k = 0; k < 16; k++) {
            float a[8], b[MN];
            *(float4*)&a[0] = *(const float4*)&As[k][ty * 8];
            *(float4*)&a[4] = *(const float4*)&As[k][ty * 8 + 4];
#pragma unroll
            for (int g = 0; g < NG; g++)
                *(float4*)&b[g * 4] = *(const float4*)&Bs[k][g * 64 + tx * 4];
#pragma unroll
            for (int i = 0; i < 8; i++)
#pragma unroll
                for (int j = 0; j < MN; j++) acc[i][j] += a[i] * b[j];
        }
        __syncthreads();
    }

#pragma unroll
    for (int i = 0; i < 8; i++) {
        int row = bm + ty * 8 + i;
        if (row >= M) continue;
#pragma unroll
        for (int g = 0; g < NG; g++) {
            int col = g * 64 + tx * 4;
            float4 v;
            v.x = acc[i][g * 4 + 0] + bias[col + 0];
            v.y = acc[i][g * 4 + 1] + bias[col + 1];
            v.z = acc[i][g * 4 + 2] + bias[col + 2];
            v.w = acc[i][g * 4 + 3] + bias[col + 3];
            if (ACT) { v.x = elu1(v.x); v.y = elu1(v.y); v.z = elu1(v.z); v.w = elu1(v.w); }
            *(float4*)(C + (size_t)row * ldc + col) = v;
        }
    }
}

// --------- layer 1 edge+softmax+aggregate+norm+bias+ELU, CSR, warp per node ---------
// H=8, C=16; lane covers 4 channels of head (lane>>2). Unshifted softmax (shift-
// invariant; logits « 88, self-loop keeps den>0).
__global__ void k_edge1_csr(const float* __restrict__ att,
                            const float* __restrict__ bias, int N) {
    int gt = blockIdx.x * blockDim.x + threadIdx.x;
    int lane = gt & 31, w = gt >> 5;
    if (w >= N) return;

    float4 attr = *(const float4*)(att + lane * 4);
    float4 b = *(const float4*)(g_xr1 + (size_t)w * 128 + lane * 4);

    int beg = g_rowptr[w], end = g_rowptr[w + 1];
    float4 acc = make_float4(0.f, 0.f, 0.f, 0.f);
    float den = 0.f;

    int s = g_esrc[beg];
    float4 a = *(const float4*)(g_xl1 + (size_t)s * 128 + lane * 4);
    for (int p = beg; p < end; p++) {
        float4 ac = a;
        if (p + 1 < end) {
            s = g_esrc[p + 1];
            a = *(const float4*)(g_xl1 + (size_t)s * 128 + lane * 4);
        }
        float z0 = ac.x + b.x; z0 = z0 > 0.f ? z0 : 0.2f * z0;
        float z1 = ac.y + b.y; z1 = z1 > 0.f ? z1 : 0.2f * z1;
        float z2 = ac.z + b.z; z2 = z2 > 0.f ? z2 : 0.2f * z2;
        float z3 = ac.w + b.w; z3 = z3 > 0.f ? z3 : 0.2f * z3;
        float part = attr.x * z0 + attr.y * z1 + attr.z * z2 + attr.w * z3;
        part += __shfl_xor_sync(0xffffffffu, part, 1);
        part += __shfl_xor_sync(0xffffffffu, part, 2);
        float ex = expf(part);
        den += ex;
        acc.x += ac.x * ex; acc.y += ac.y * ex;
        acc.z += ac.z * ex; acc.w += ac.w * ex;
    }

    float inv = 1.f / den;
    int c = lane * 4;
    float4 o;
    o.x = elu1(acc.x * inv + bias[c + 0]);
    o.y = elu1(acc.y * inv + bias[c + 1]);
    o.z = elu1(acc.z * inv + bias[c + 2]);
    o.w = elu1(acc.w * inv + bias[c + 3]);
    *(float4*)(g_h1 + (size_t)w * 128 + c) = o;
}

// --------- layer 2 edge pass, CSR, warp per node; H=1, C=64; lane = 2 channels ---------
__global__ void k_edge2_csr(const float* __restrict__ att,
                            const float* __restrict__ bias, int N) {
    int gt = blockIdx.x * blockDim.x + threadIdx.x;
    int lane = gt & 31, w = gt >> 5;
    if (w >= N) return;

    float2 attr = *(const float2*)(att + lane * 2);
    float2 b = *(const float2*)(g_xr2 + (size_t)w * 64 + lane * 2);

    int beg = g_rowptr[w], end = g_rowptr[w + 1];
    float2 acc = make_float2(0.f, 0.f);
    float den = 0.f;

    int s = g_esrc[beg];
    float2 a = *(const float2*)(g_xl2 + (size_t)s * 64 + lane * 2);
    for (int p = beg; p < end; p++) {
        float2 ac = a;
        if (p + 1 < end) {
            s = g_esrc[p + 1];
            a = *(const float2*)(g_xl2 + (size_t)s * 64 + lane * 2);
        }
        float z0 = ac.x + b.x; z0 = z0 > 0.f ? z0 : 0.2f * z0;
        float z1 = ac.y + b.y; z1 = z1 > 0.f ? z1 : 0.2f * z1;
        float part = attr.x * z0 + attr.y * z1;
        part += __shfl_xor_sync(0xffffffffu, part, 1);
        part += __shfl_xor_sync(0xffffffffu, part, 2);
        part += __shfl_xor_sync(0xffffffffu, part, 4);
        part += __shfl_xor_sync(0xffffffffu, part, 8);
        part += __shfl_xor_sync(0xffffffffu, part, 16);
        float ex = expf(part);
        den += ex;
        acc.x += ac.x * ex; acc.y += ac.y * ex;
    }

    float inv = 1.f / den;
    int c = lane * 2;
    float2 o;
    o.x = elu1(acc.x * inv + bias[c + 0]);
    o.y = elu1(acc.y * inv + bias[c + 1]);
    *(float2*)(g_h2 + (size_t)w * 64 + c) = o;
}

// ------------------------- launch -------------------------
static inline int cdiv(int a, int b) { return (a + b - 1) / b; }

extern "C" void kernel_launch(void* const* d_in, const int* in_sizes, int n_in,
                              void* d_out, int out_size) {
    const float* x     = (const float*)d_in[0];
    const int*   ei    = (const int*)d_in[1];
    const float* Wl1   = (const float*)d_in[2];
    const float* bl1   = (const float*)d_in[3];
    const float* Wr1   = (const float*)d_in[4];
    const float* br1   = (const float*)d_in[5];
    const float* att1  = (const float*)d_in[6];
    const float* bias1 = (const float*)d_in[7];
    const float* Wl2   = (const float*)d_in[8];
    const float* bl2   = (const float*)d_in[9];
    const float* Wr2   = (const float*)d_in[10];
    const float* br2   = (const float*)d_in[11];
    const float* att2  = (const float*)d_in[12];
    const float* bias2 = (const float*)d_in[13];
    const float* Wlin  = (const float*)d_in[14];
    const float* blin  = (const float*)d_in[15];

    int N = in_sizes[0] / 128;
    int E = in_sizes[1] / 2;
    int Etot = E + N;
    int NB = cdiv(N, 256);

    // ---- CSR build (dst-sorted, self-loop first per segment) ----
    k_initdeg<<<NB, 256>>>(N);
    k_hist<<<cdiv(E, 256), 256>>>(ei, E);
    k_scanblk<<<NB, 256>>>(N);
    k_scantop<<<1, 256>>>(NB);
    k_finalize<<<NB, 256>>>(N, Etot);
    k_scatter<<<cdiv(E, 256), 256>>>(ei, E);

    // ---- layer 1: GATv2 (H=8, C=16, concat) ----
    dim3 g1(cdiv(N, 128), 2);
    k_gemm<128, 128, 0, 0, 1><<<g1, 256>>>(x, Wl1, Wr1, bl1, br1, nullptr, N);
    k_edge1_csr<<<cdiv(N * 32, 256), 256>>>(att1, bias1, N);

    // ---- layer 2: GATv2 (H=1, C=64) ----
    dim3 g2(cdiv(N, 128), 2);
    k_gemm<128, 64, 0, 1, 2><<<g2, 256>>>(nullptr, Wl2, Wr2, bl2, br2, nullptr, N);
    k_edge2_csr<<<cdiv(N * 32, 256), 256>>>(att2, bias2, N);

    // ---- final linear + ELU -> d_out [N,128] ----
    dim3 g3(cdiv(N, 128), 1);
    k_gemm<64, 128, 1, 2, 0><<<g3, 256>>>(nullptr, Wlin, Wlin, blin, blin, (float*)d_out, N);
}

// round 6
// speedup vs baseline: 2.3062x; 1.0066x over previous
#include <cuda_runtime.h>
#include <cstdint>

#define NMAX    50048
#define EMAX    800000
#define ETOTMAX (NMAX + EMAX)
#define NBLKMAX 256

// ------------------------- scratch (device globals) -------------------------
__device__ __align__(16) float g_xl1[NMAX * 128];
__device__ __align__(16) float g_xr1[NMAX * 128];
__device__ __align__(16) float g_h1[NMAX * 128];
__device__ __align__(16) float g_xl2[NMAX * 64];
__device__ __align__(16) float g_xr2[NMAX * 64];
__device__ __align__(16) float g_h2[NMAX * 64];
__device__ __align__(16) int   g_deg[NMAX];
__device__ __align__(16) int   g_pre[NMAX];
__device__ __align__(16) int   g_bsum[NBLKMAX];
__device__ __align__(16) int   g_rowptr[NMAX + 1];
__device__ __align__(16) int   g_cursor[NMAX];
__device__ __align__(16) int   g_esrc[ETOTMAX];

// ------------------------- helpers -------------------------
__device__ __forceinline__ float elu1(float v) { return v > 0.f ? v : expm1f(v); }

__device__ __forceinline__ uint32_t f2tf32(float x) {
    uint32_t r;
    asm("cvt.rna.tf32.f32 %0, %1;" : "=r"(r) : "f"(x));
    return r;
}

__device__ __forceinline__ void mma_tf32(float* c, const uint32_t* a, const uint32_t* b) {
    asm volatile(
        "mma.sync.aligned.m16n8k8.row.col.f32.tf32.tf32.f32 "
        "{%0,%1,%2,%3}, {%4,%5,%6,%7}, {%8,%9}, {%0,%1,%2,%3};\n"
        : "+f"(c[0]), "+f"(c[1]), "+f"(c[2]), "+f"(c[3])
        : "r"(a[0]), "r"(a[1]), "r"(a[2]), "r"(a[3]), "r"(b[0]), "r"(b[1]));
}

// ------------------------- CSR build -------------------------
__global__ void k_initdeg(int N) {
    int i = blockIdx.x * blockDim.x + threadIdx.x;
    if (i < N) g_deg[i] = 1;              // self-loop
}
__global__ void k_hist(const int* __restrict__ ei, int E) {
    int i = blockIdx.x * blockDim.x + threadIdx.x;
    if (i < E) atomicAdd(&g_deg[ei[E + i]], 1);
}
__global__ void k_scanblk(int N) {
    __shared__ int sh[256];
    int i = blockIdx.x * 256 + threadIdx.x;
    int v = (i < N) ? g_deg[i] : 0;
    sh[threadIdx.x] = v;
    __syncthreads();
    for (int off = 1; off < 256; off <<= 1) {
        int t = (threadIdx.x >= off) ? sh[threadIdx.x - off] : 0;
        __syncthreads();
        sh[threadIdx.x] += t;
        __syncthreads();
    }
    if (i < N) g_pre[i] = sh[threadIdx.x] - v;   // exclusive
    if (threadIdx.x == 255) g_bsum[blockIdx.x] = sh[255];
}
__global__ void k_scantop(int NB) {
    __shared__ int sh[256];
    int v = (threadIdx.x < NB) ? g_bsum[threadIdx.x] : 0;
    sh[threadIdx.x] = v;
    __syncthreads();
    for (int off = 1; off < 256; off <<= 1) {
        int t = (threadIdx.x >= off) ? sh[threadIdx.x - off] : 0;
        __syncthreads();
        sh[threadIdx.x] += t;
        __syncthreads();
    }
    if (threadIdx.x < NB) g_bsum[threadIdx.x] = sh[threadIdx.x] - v;  // exclusive
}
__global__ void k_finalize(int N, int Etot) {
    int i = blockIdx.x * blockDim.x + threadIdx.x;
    if (i < N) {
        int rp = g_pre[i] + g_bsum[i >> 8];
        g_rowptr[i] = rp;
        g_cursor[i] = rp + 1;
        g_esrc[rp] = i;                   // self-loop occupies first slot
        if (i == 0) g_rowptr[N] = Etot;
    }
}
__global__ void k_scatter(const int* __restrict__ ei, int E) {
    int i = blockIdx.x * blockDim.x + threadIdx.x;
    if (i < E) {
        int d = ei[E + i];
        int slot = atomicAdd(&g_cursor[d], 1);
        g_esrc[slot] = ei[i];
    }
}

// --------------- 3xTF32 tensor-core GEMM: C = A[M,K] @ W[K,BN] + bias ---------------
// BM=128, BK=16, 256 threads = 8 warps (2 m-warps x 4 n-warps).
// SRC: 0 = Aarg, 1 = g_h1, 2 = g_h2.
// DSTSEL: 0 = Carg (ldc=BN), 1 = y-select (xl1,xr1) ldc=128, 2 = y-select (xl2,xr2) ldc=64.
template <int K, int BN, int ACT, int SRC, int DSTSEL>
__global__ __launch_bounds__(256) void k_gemm_tc(const float* __restrict__ Aarg,
                                                 const float* __restrict__ W0,
                                                 const float* __restrict__ W1,
                                                 const float* __restrict__ b0,
                                                 const float* __restrict__ b1,
                                                 float* __restrict__ Carg, int M) {
    const int NF = BN / 32;                 // n-fragments per warp (4 or 2)
    const int ASTR = 20;                    // padded A row stride (conflict-free frags)
    const int BSTR = BN + 8;                // padded B row stride

    const float* A = (SRC == 0) ? Aarg : (SRC == 1 ? g_h1 : g_h2);
    const float* W    = (blockIdx.y == 0) ? W0 : W1;
    const float* bias = (blockIdx.y == 0) ? b0 : b1;
    float* C;
    int ldc;
    if (DSTSEL == 0)      { C = Carg; ldc = BN; }
    else if (DSTSEL == 1) { C = (blockIdx.y == 0) ? g_xl1 : g_xr1; ldc = 128; }
    else                  { C = (blockIdx.y == 0) ? g_xl2 : g_xr2; ldc = 64; }

    __shared__ float Ah[128][ASTR];
    __shared__ float Al[128][ASTR];
    __shared__ float Bh[16][BSTR];
    __shared__ float Bl[16][BSTR];

    int tid  = threadIdx.x;
    int lane = tid & 31;
    int ww   = tid >> 5;
    int bm   = blockIdx.x * 128;
    int wm0  = (ww & 1) * 64;              // warp m offset (2 warps)
    int wn0  = (ww >> 1) * (BN / 4);       // warp n offset (4 warps)
    int tg   = lane & 3;                   // threadID_in_group
    int gid  = lane >> 2;                  // groupID

    float acc[4][NF][4] = {};

#pragma unroll 1
    for (int k0 = 0; k0 < K; k0 += 16) {
        // A tile: 128 rows x 16 cols, split hi/lo tf32
        {
            int row = tid >> 1;
            int arow = bm + row; if (arow >= M) arow = M - 1;
#pragma unroll
            for (int r = 0; r < 2; r++) {
                int cq = (tid & 1) * 2 + r;
                float4 v = *(const float4*)(A + (size_t)arow * K + k0 + cq * 4);
                float4 h, l;
                h.x = __uint_as_float(f2tf32(v.x)); l.x = __uint_as_float(f2tf32(v.x - h.x));
                h.y = __uint_as_float(f2tf32(v.y)); l.y = __uint_as_float(f2tf32(v.y - h.y));
                h.z = __uint_as_float(f2tf32(v.z)); l.z = __uint_as_float(f2tf32(v.z - h.z));
                h.w = __uint_as_float(f2tf32(v.w)); l.w = __uint_as_float(f2tf32(v.w - h.w));
                *(float4*)&Ah[row][cq * 4] = h;
                *(float4*)&Al[row][cq * 4] = l;
            }
        }
        // B tile: 16 rows x BN, split hi/lo tf32
        {
            const int NF4 = BN / 4;
#pragma unroll
            for (int q = tid; q < 16 * NF4; q += 256) {
                int row = q / NF4, cf = q % NF4;
                float4 v = *(const float4*)(W + (size_t)(k0 + row) * BN + cf * 4);
                float4 h, l;
                h.x = __uint_as_float(f2tf32(v.x)); l.x = __uint_as_float(f2tf32(v.x - h.x));
                h.y = __uint_as_float(f2tf32(v.y)); l.y = __uint_as_float(f2tf32(v.y - h.y));
                h.z = __uint_as_float(f2tf32(v.z)); l.z = __uint_as_float(f2tf32(v.z - h.z));
                h.w = __uint_as_float(f2tf32(v.w)); l.w = __uint_as_float(f2tf32(v.w - h.w));
                *(float4*)&Bh[row][cf * 4] = h;
                *(float4*)&Bl[row][cf * 4] = l;
            }
        }
        __syncthreads();

#pragma unroll
        for (int ks = 0; ks < 2; ks++) {
            int kb = ks * 8;
            uint32_t ah[4][4], al[4][4];
#pragma unroll
            for (int im = 0; im < 4; im++) {
                int mr = wm0 + im * 16 + gid;
                ah[im][0] = __float_as_uint(Ah[mr][kb + tg]);
                ah[im][1] = __float_as_uint(Ah[mr + 8][kb + tg]);
                ah[im][2] = __float_as_uint(Ah[mr][kb + tg + 4]);
                ah[im][3] = __float_as_uint(Ah[mr + 8][kb + tg + 4]);
                al[im][0] = __float_as_uint(Al[mr][kb + tg]);
                al[im][1] = __float_as_uint(Al[mr + 8][kb + tg]);
                al[im][2] = __float_as_uint(Al[mr][kb + tg + 4]);
                al[im][3] = __float_as_uint(Al[mr + 8][kb + tg + 4]);
            }
            uint32_t bh[NF][2], bl[NF][2];
#pragma unroll
            for (int in = 0; in < NF; in++) {
                int nc = wn0 + in * 8 + gid;
                bh[in][0] = __float_as_uint(Bh[kb + tg][nc]);
                bh[in][1] = __float_as_uint(Bh[kb + tg + 4][nc]);
                bl[in][0] = __float_as_uint(Bl[kb + tg][nc]);
                bl[in][1] = __float_as_uint(Bl[kb + tg + 4][nc]);
            }
#pragma unroll
            for (int im = 0; im < 4; im++)
#pragma unroll
                for (int in = 0; in < NF; in++) {
                    mma_tf32(acc[im][in], ah[im], bh[in]);
                    mma_tf32(acc[im][in], al[im], bh[in]);
                    mma_tf32(acc[im][in], ah[im], bl[in]);
                }
        }
        __syncthreads();
    }

    // epilogue: bias (+ELU), float2 stores per c-fragment half
#pragma unroll
    for (int im = 0; im < 4; im++) {
        int r0 = bm + wm0 + im * 16 + gid;
#pragma unroll
        for (int in = 0; in < NF; in++) {
            int cc = wn0 + in * 8 + 2 * tg;
            float bx = bias[cc], by = bias[cc + 1];
            if (r0 < M) {
                float2 v = make_float2(acc[im][in][0] + bx, acc[im][in][1] + by);
                if (ACT) { v.x = elu1(v.x); v.y = elu1(v.y); }
                *(float2*)(C + (size_t)r0 * ldc + cc) = v;
            }
            if (r0 + 8 < M) {
                float2 v = make_float2(acc[im][in][2] + bx, acc[im][in][3] + by);
                if (ACT) { v.x = elu1(v.x); v.y = elu1(v.y); }
                *(float2*)(C + (size_t)(r0 + 8) * ldc + cc) = v;
            }
        }
    }
}

// --------- layer 1 edge+softmax+aggregate+norm+bias+ELU, CSR, warp per node ---------
// H=8, C=16; lane covers 4 channels of head (lane>>2). Unshifted softmax (shift-
// invariant; logits « 88, self-loop keeps den>0).
__global__ void k_edge1_csr(const float* __restrict__ att,
                            const float* __restrict__ bias, int N) {
    int gt = blockIdx.x * blockDim.x + threadIdx.x;
    int lane = gt & 31, w = gt >> 5;
    if (w >= N) return;

    float4 attr = *(const float4*)(att + lane * 4);
    float4 b = *(const float4*)(g_xr1 + (size_t)w * 128 + lane * 4);

    int beg = g_rowptr[w], end = g_rowptr[w + 1];
    float4 acc = make_float4(0.f, 0.f, 0.f, 0.f);
    float den = 0.f;

    int s = g_esrc[beg];
    float4 a = *(const float4*)(g_xl1 + (size_t)s * 128 + lane * 4);
    for (int p = beg; p < end; p++) {
        float4 ac = a;
        if (p + 1 < end) {
            s = g_esrc[p + 1];
            a = *(const float4*)(g_xl1 + (size_t)s * 128 + lane * 4);
        }
        float z0 = ac.x + b.x; z0 = z0 > 0.f ? z0 : 0.2f * z0;
        float z1 = ac.y + b.y; z1 = z1 > 0.f ? z1 : 0.2f * z1;
        float z2 = ac.z + b.z; z2 = z2 > 0.f ? z2 : 0.2f * z2;
        float z3 = ac.w + b.w; z3 = z3 > 0.f ? z3 : 0.2f * z3;
        float part = attr.x * z0 + attr.y * z1 + attr.z * z2 + attr.w * z3;
        part += __shfl_xor_sync(0xffffffffu, part, 1);
        part += __shfl_xor_sync(0xffffffffu, part, 2);
        float ex = expf(part);
        den += ex;
        acc.x += ac.x * ex; acc.y += ac.y * ex;
        acc.z += ac.z * ex; acc.w += ac.w * ex;
    }

    float inv = 1.f / den;
    int c = lane * 4;
    float4 o;
    o.x = elu1(acc.x * inv + bias[c + 0]);
    o.y = elu1(acc.y * inv + bias[c + 1]);
    o.z = elu1(acc.z * inv + bias[c + 2]);
    o.w = elu1(acc.w * inv + bias[c + 3]);
    *(float4*)(g_h1 + (size_t)w * 128 + c) = o;
}

// --------- layer 2 edge pass, CSR, warp per node; H=1, C=64; lane = 2 channels ---------
__global__ void k_edge2_csr(const float* __restrict__ att,
                            const float* __restrict__ bias, int N) {
    int gt = blockIdx.x * blockDim.x + threadIdx.x;
    int lane = gt & 31, w = gt >> 5;
    if (w >= N) return;

    float2 attr = *(const float2*)(att + lane * 2);
    float2 b = *(const float2*)(g_xr2 + (size_t)w * 64 + lane * 2);

    int beg = g_rowptr[w], end = g_rowptr[w + 1];
    float2 acc = make_float2(0.f, 0.f);
    float den = 0.f;

    int s = g_esrc[beg];
    float2 a = *(const float2*)(g_xl2 + (size_t)s * 64 + lane * 2);
    for (int p = beg; p < end; p++) {
        float2 ac = a;
        if (p + 1 < end) {
            s = g_esrc[p + 1];
            a = *(const float2*)(g_xl2 + (size_t)s * 64 + lane * 2);
        }
        float z0 = ac.x + b.x; z0 = z0 > 0.f ? z0 : 0.2f * z0;
        float z1 = ac.y + b.y; z1 = z1 > 0.f ? z1 : 0.2f * z1;
        float part = attr.x * z0 + attr.y * z1;
        part += __shfl_xor_sync(0xffffffffu, part, 1);
        part += __shfl_xor_sync(0xffffffffu, part, 2);
        part += __shfl_xor_sync(0xffffffffu, part, 4);
        part += __shfl_xor_sync(0xffffffffu, part, 8);
        part += __shfl_xor_sync(0xffffffffu, part, 16);
        float ex = expf(part);
        den += ex;
        acc.x += ac.x * ex; acc.y += ac.y * ex;
    }

    float inv = 1.f / den;
    int c = lane * 2;
    float2 o;
    o.x = elu1(acc.x * inv + bias[c + 0]);
    o.y = elu1(acc.y * inv + bias[c + 1]);
    *(float2*)(g_h2 + (size_t)w * 64 + c) = o;
}

// ------------------------- launch -------------------------
static inline int cdiv(int a, int b) { return (a + b - 1) / b; }

extern "C" void kernel_launch(void* const* d_in, const int* in_sizes, int n_in,
                              void* d_out, int out_size) {
    const float* x     = (const float*)d_in[0];
    const int*   ei    = (const int*)d_in[1];
    const float* Wl1   = (const float*)d_in[2];
    const float* bl1   = (const float*)d_in[3];
    const float* Wr1   = (const float*)d_in[4];
    const float* br1   = (const float*)d_in[5];
    const float* att1  = (const float*)d_in[6];
    const float* bias1 = (const float*)d_in[7];
    const float* Wl2   = (const float*)d_in[8];
    const float* bl2   = (const float*)d_in[9];
    const float* Wr2   = (const float*)d_in[10];
    const float* br2   = (const float*)d_in[11];
    const float* att2  = (const float*)d_in[12];
    const float* bias2 = (const float*)d_in[13];
    const float* Wlin  = (const float*)d_in[14];
    const float* blin  = (const float*)d_in[15];

    int N = in_sizes[0] / 128;
    int E = in_sizes[1] / 2;
    int Etot = E + N;
    int NB = cdiv(N, 256);

    // ---- CSR build (dst-sorted, self-loop first per segment) ----
    k_initdeg<<<NB, 256>>>(N);
    k_hist<<<cdiv(E, 256), 256>>>(ei, E);
    k_scanblk<<<NB, 256>>>(N);
    k_scantop<<<1, 256>>>(NB);
    k_finalize<<<NB, 256>>>(N, Etot);
    k_scatter<<<cdiv(E, 256), 256>>>(ei, E);

    // ---- layer 1: GATv2 (H=8, C=16, concat) ----
    dim3 g1(cdiv(N, 128), 2);
    k_gemm_tc<128, 128, 0, 0, 1><<<g1, 256>>>(x, Wl1, Wr1, bl1, br1, nullptr, N);
    k_edge1_csr<<<cdiv(N * 32, 256), 256>>>(att1, bias1, N);

    // ---- layer 2: GATv2 (H=1, C=64) ----
    dim3 g2(cdiv(N, 128), 2);
    k_gemm_tc<128, 64, 0, 1, 2><<<g2, 256>>>(nullptr, Wl2, Wr2, bl2, br2, nullptr, N);
    k_edge2_csr<<<cdiv(N * 32, 256), 256>>>(att2, bias2, N);

    // ---- final linear + ELU -> d_out [N,128] ----
    dim3 g3(cdiv(N, 128), 1);
    k_gemm_tc<64, 128, 1, 2, 0><<<g3, 256>>>(nullptr, Wlin, Wlin, blin, blin, (float*)d_out, N);
}